// round 1
// baseline (speedup 1.0000x reference)
#include <cuda_runtime.h>
#include <math.h>

#define NTOK 2048
#define DIM  768
#define FF   3072
#define NE   8
#define NL   4
#define NA   (NTOK*2)   // total expert assignments per layer (top-2)

#define BM 128
#define BN 64
#define BK 16
#define PAD 4

// ---------------- scratch (static device globals; no allocation) -------------
__device__ float g_h   [NTOK*DIM];          // residual stream
__device__ float g_xln [NTOK*DIM];          // per-layer LN output
__device__ float g_tmp [NTOK*DIM];          // projection temp
__device__ float g_H1  [(size_t)NA*FF];     // expert hidden activations (50MB)
__device__ float g_Y   [NA*DIM];            // per (token,slot) expert outputs
__device__ int   g_counts[NL*NE];
__device__ int   g_cursor[NL*NE];
__device__ int   g_off   [NL*(NE+1)];
__device__ int   g_tok [NA];                // assignment -> token
__device__ int   g_pair[NA];                // assignment -> token*2+slot
__device__ float g_gw  [NA];                // assignment -> gate weight
__device__ int   g_re  [NTOK*2];            // token routing: expert ids (sorted by logit)
__device__ float g_rw  [NTOK*2];            // token routing: softmax weights

// ---------------- utilities --------------------------------------------------
__device__ __forceinline__ float warpSum(float v) {
    #pragma unroll
    for (int o = 16; o > 0; o >>= 1) v += __shfl_xor_sync(0xffffffffu, v, o);
    return v;
}

__global__ void zero_k() {
    int i = threadIdx.x;
    if (i < NL*NE) { g_counts[i] = 0; g_cursor[i] = 0; }
}

// ---------------- LayerNorm (+ optional gate / top-2 routing) ---------------
// One block (256 threads) per token.
__global__ void ln_gate(const float* __restrict__ in, float* __restrict__ out,
                        const float* __restrict__ gam, const float* __restrict__ bet,
                        const float* __restrict__ wg, int layer)
{
    __shared__ float s[DIM];
    __shared__ float red[8];
    __shared__ float sstat;
    __shared__ float logits[NE];

    const int t = blockIdx.x, tid = threadIdx.x;
    const int lane = tid & 31, wid = tid >> 5;
    const float* row = in + (size_t)t*DIM;

    float lsum = 0.f;
    for (int d = tid; d < DIM; d += 256) { float v = row[d]; s[d] = v; lsum += v; }
    lsum = warpSum(lsum);
    if (lane == 0) red[wid] = lsum;
    __syncthreads();
    if (tid == 0) { float z = 0.f; for (int i = 0; i < 8; i++) z += red[i]; sstat = z / DIM; }
    __syncthreads();
    const float mu = sstat;

    float lvar = 0.f;
    for (int d = tid; d < DIM; d += 256) { float dv = s[d] - mu; lvar += dv*dv; }
    lvar = warpSum(lvar);
    __syncthreads();            // red + sstat reuse safe
    if (lane == 0) red[wid] = lvar;
    __syncthreads();
    if (tid == 0) { float z = 0.f; for (int i = 0; i < 8; i++) z += red[i]; sstat = rsqrtf(z / DIM + 1e-5f); }
    __syncthreads();
    const float rstd = sstat;

    for (int d = tid; d < DIM; d += 256) {
        float o = (s[d] - mu) * rstd * gam[d] + bet[d];
        out[(size_t)t*DIM + d] = o;
        s[d] = o;
    }
    if (!wg) return;
    __syncthreads();

    // 8 warps, one logit each: logits[e] = dot(ln_row, wg[:, e])
    float acc = 0.f;
    for (int d = lane; d < DIM; d += 32) acc += s[d] * wg[d*NE + wid];
    acc = warpSum(acc);
    if (lane == 0) logits[wid] = acc;
    __syncthreads();

    if (tid == 0) {
        float v0 = -1e30f; int e0 = 0;
        #pragma unroll
        for (int e = 0; e < NE; e++) if (logits[e] > v0) { v0 = logits[e]; e0 = e; }
        float v1 = -1e30f; int e1 = 0;
        #pragma unroll
        for (int e = 0; e < NE; e++) if (e != e0 && logits[e] > v1) { v1 = logits[e]; e1 = e; }
        float ex  = expf(v1 - v0);
        float inv = 1.f / (1.f + ex);
        g_re[2*t] = e0;  g_re[2*t+1] = e1;
        g_rw[2*t] = inv; g_rw[2*t+1] = ex * inv;
        atomicAdd(&g_counts[layer*NE + e0], 1);
        atomicAdd(&g_counts[layer*NE + e1], 1);
    }
}

__global__ void scan_k(int layer) {
    if (threadIdx.x == 0) {
        int s = 0;
        for (int e = 0; e < NE; e++) { g_off[layer*(NE+1) + e] = s; s += g_counts[layer*NE + e]; }
        g_off[layer*(NE+1) + NE] = s;
    }
}

__global__ void scatter_k(int layer) {
    int t = blockIdx.x * blockDim.x + threadIdx.x;
    if (t >= NTOK) return;
    #pragma unroll
    for (int k = 0; k < 2; k++) {
        int e = g_re[2*t + k];
        int p = atomicAdd(&g_cursor[layer*NE + e], 1);
        int i = g_off[layer*(NE+1) + e] + p;
        g_tok[i]  = t;
        g_pair[i] = 2*t + k;
        g_gw[i]   = g_rw[2*t + k];
    }
}

// ---------------- dense GEMM: C = A*B + bias ---------------------------------
__global__ void __launch_bounds__(256)
gemm_basic(const float* __restrict__ A, const float* __restrict__ B,
           const float* __restrict__ bias, float* __restrict__ C,
           int M, int Nn, int Kd)
{
    __shared__ float As[BK][BM+PAD];
    __shared__ float Bs[BK][BN];
    const int tid = threadIdx.x;
    const int tx = tid & 15, ty = tid >> 4;
    const int m0 = blockIdx.y * BM, n0 = blockIdx.x * BN;

    float acc[8][4];
    #pragma unroll
    for (int i = 0; i < 8; i++)
        #pragma unroll
        for (int j = 0; j < 4; j++) acc[i][j] = 0.f;

    for (int kt = 0; kt < Kd; kt += BK) {
        #pragma unroll
        for (int j = 0; j < 8; j++) {
            int idx = tid + j*256;
            int k = idx & 15, m = idx >> 4;
            int gm = m0 + m;
            As[k][m] = (gm < M) ? A[(size_t)gm*Kd + kt + k] : 0.f;
        }
        #pragma unroll
        for (int j = 0; j < 4; j++) {
            int idx = tid + j*256;
            int n = idx & 63, k = idx >> 6;
            Bs[k][n] = B[(size_t)(kt + k)*Nn + n0 + n];
        }
        __syncthreads();
        #pragma unroll
        for (int kk = 0; kk < BK; kk++) {
            float4 a0 = *(const float4*)&As[kk][ty*8];
            float4 a1 = *(const float4*)&As[kk][ty*8 + 4];
            float4 b0 = *(const float4*)&Bs[kk][tx*4];
            float av[8] = {a0.x,a0.y,a0.z,a0.w,a1.x,a1.y,a1.z,a1.w};
            float bv[4] = {b0.x,b0.y,b0.z,b0.w};
            #pragma unroll
            for (int i = 0; i < 8; i++)
                #pragma unroll
                for (int j = 0; j < 4; j++)
                    acc[i][j] += av[i]*bv[j];
        }
        __syncthreads();
    }
    #pragma unroll
    for (int i = 0; i < 8; i++) {
        int gm = m0 + ty*8 + i;
        if (gm >= M) continue;
        #pragma unroll
        for (int j = 0; j < 4; j++) {
            int gn = n0 + tx*4 + j;
            C[(size_t)gm*Nn + gn] = acc[i][j] + bias[gn];
        }
    }
}

// ---------------- expert GEMMs (gathered A rows) ----------------------------
// mode 0: H1[i,:] = relu(xln[tok[i],:] @ w1[l,e] + b1[l,e])     (Nn=FF, Kd=DIM)
// mode 1: Y[pair[i],:] = gw[i] * (H1[i,:] @ w2[l,e] + b2[l,e])  (Nn=DIM, Kd=FF)
__global__ void __launch_bounds__(256)
expert_gemm(int mode, int layer,
            const float* __restrict__ w1, const float* __restrict__ b1,
            const float* __restrict__ w2, const float* __restrict__ b2)
{
    const int e   = blockIdx.z;
    const int cnt = g_counts[layer*NE + e];
    const int m0  = blockIdx.y * BM;
    if (m0 >= cnt) return;
    const int base = g_off[layer*(NE+1) + e];

    const int Nn = (mode == 0) ? FF : DIM;
    const int Kd = (mode == 0) ? DIM : FF;
    const size_t wo = (size_t)(layer*NE + e);
    const float* Bmat = (mode == 0) ? (w1 + wo*(size_t)DIM*FF) : (w2 + wo*(size_t)FF*DIM);
    const float* bias = (mode == 0) ? (b1 + wo*FF) : (b2 + wo*DIM);

    __shared__ float As[BK][BM+PAD];
    __shared__ float Bs[BK][BN];
    const int tid = threadIdx.x;
    const int tx = tid & 15, ty = tid >> 4;
    const int n0 = blockIdx.x * BN;

    // per-thread A source row pointers (fixed across k-tiles)
    const float* arow[8];
    int koff[8], msh[8];
    #pragma unroll
    for (int j = 0; j < 8; j++) {
        int idx = tid + j*256;
        koff[j] = idx & 15; msh[j] = idx >> 4;
        int lm = m0 + msh[j];
        if (lm < cnt) {
            int gi = base + lm;
            arow[j] = (mode == 0) ? (g_xln + (size_t)g_tok[gi]*DIM)
                                  : (g_H1  + (size_t)gi*FF);
        } else arow[j] = nullptr;
    }

    float acc[8][4];
    #pragma unroll
    for (int i = 0; i < 8; i++)
        #pragma unroll
        for (int j = 0; j < 4; j++) acc[i][j] = 0.f;

    for (int kt = 0; kt < Kd; kt += BK) {
        #pragma unroll
        for (int j = 0; j < 8; j++)
            As[koff[j]][msh[j]] = arow[j] ? arow[j][kt + koff[j]] : 0.f;
        #pragma unroll
        for (int j = 0; j < 4; j++) {
            int idx = tid + j*256;
            int n = idx & 63, k = idx >> 6;
            Bs[k][n] = Bmat[(size_t)(kt + k)*Nn + n0 + n];
        }
        __syncthreads();
        #pragma unroll
        for (int kk = 0; kk < BK; kk++) {
            float4 a0 = *(const float4*)&As[kk][ty*8];
            float4 a1 = *(const float4*)&As[kk][ty*8 + 4];
            float4 b0 = *(const float4*)&Bs[kk][tx*4];
            float av[8] = {a0.x,a0.y,a0.z,a0.w,a1.x,a1.y,a1.z,a1.w};
            float bv[4] = {b0.x,b0.y,b0.z,b0.w};
            #pragma unroll
            for (int i = 0; i < 8; i++)
                #pragma unroll
                for (int j = 0; j < 4; j++)
                    acc[i][j] += av[i]*bv[j];
        }
        __syncthreads();
    }

    #pragma unroll
    for (int i = 0; i < 8; i++) {
        int lm = m0 + ty*8 + i;
        if (lm >= cnt) continue;
        int gi = base + lm;
        if (mode == 0) {
            float* Crow = g_H1 + (size_t)gi*FF;
            #pragma unroll
            for (int j = 0; j < 4; j++) {
                int gn = n0 + tx*4 + j;
                Crow[gn] = fmaxf(acc[i][j] + bias[gn], 0.f);
            }
        } else {
            float w = g_gw[gi];
            float* Crow = g_Y + (size_t)g_pair[gi]*DIM;
            #pragma unroll
            for (int j = 0; j < 4; j++) {
                int gn = n0 + tx*4 + j;
                Crow[gn] = w * (acc[i][j] + bias[gn]);
            }
        }
    }
}

// h += y(slot0) + y(slot1), fixed order -> deterministic
__global__ void combine_k() {
    int idx = blockIdx.x * 256 + threadIdx.x;
    int t = idx / DIM, d = idx - t*DIM;
    float v = g_h[idx];
    v = v + g_Y[(size_t)(2*t)*DIM + d];
    v = v + g_Y[(size_t)(2*t + 1)*DIM + d];
    g_h[idx] = v;
}

// ---------------- host -------------------------------------------------------
extern "C" void kernel_launch(void* const* d_in, const int* in_sizes, int n_in,
                              void* d_out, int out_size)
{
    (void)in_sizes; (void)n_in; (void)out_size;
    const float* x      = (const float*)d_in[0];
    const float* w_in   = (const float*)d_in[1];
    const float* b_in   = (const float*)d_in[2];
    const float* gi     = (const float*)d_in[3];
    const float* bi     = (const float*)d_in[4];
    const float* g_lnp  = (const float*)d_in[5];
    const float* be_lnp = (const float*)d_in[6];
    const float* wgp    = (const float*)d_in[7];
    const float* w1p    = (const float*)d_in[8];
    const float* b1p    = (const float*)d_in[9];
    const float* w2p    = (const float*)d_in[10];
    const float* b2p    = (const float*)d_in[11];
    const float* w_out  = (const float*)d_in[12];
    const float* b_out  = (const float*)d_in[13];
    const float* g_o    = (const float*)d_in[14];
    const float* be_o   = (const float*)d_in[15];

    float *hP, *tmpP, *xlnP;
    cudaGetSymbolAddress((void**)&hP,   g_h);
    cudaGetSymbolAddress((void**)&tmpP, g_tmp);
    cudaGetSymbolAddress((void**)&xlnP, g_xln);

    zero_k<<<1, 64>>>();

    // input projection + LN -> residual stream h
    gemm_basic<<<dim3(DIM/BN, NTOK/BM), 256>>>(x, w_in, b_in, tmpP, NTOK, DIM, DIM);
    ln_gate<<<NTOK, 256>>>(tmpP, hP, gi, bi, nullptr, 0);

    for (int l = 0; l < NL; l++) {
        ln_gate<<<NTOK, 256>>>(hP, xlnP, g_lnp + (size_t)l*DIM, be_lnp + (size_t)l*DIM,
                               wgp + (size_t)l*DIM*NE, l);
        scan_k<<<1, 32>>>(l);
        scatter_k<<<NTOK/256, 256>>>(l);
        expert_gemm<<<dim3(FF/BN,  NTOK/BM, NE), 256>>>(0, l, w1p, b1p, w2p, b2p);
        expert_gemm<<<dim3(DIM/BN, NTOK/BM, NE), 256>>>(1, l, w1p, b1p, w2p, b2p);
        combine_k<<<NTOK*DIM/256, 256>>>();
    }

    // output projection + LN -> d_out
    gemm_basic<<<dim3(DIM/BN, NTOK/BM), 256>>>(hP, w_out, b_out, tmpP, NTOK, DIM, DIM);
    ln_gate<<<NTOK, 256>>>(tmpP, (float*)d_out, g_o, be_o, nullptr, 0);
}

// round 4
// speedup vs baseline: 1.5578x; 1.5578x over previous
#include <cuda_runtime.h>
#include <math.h>
#include <stdint.h>

#define NTOK 2048
#define DIM  768
#define FF   3072
#define NE   8
#define NL   4
#define NA   (NTOK*2)

// smem layout (float words): Ah[128][36], Al[128][36], Bh[32][136], Bl[32][136]
#define AW 36
#define BW 136
#define OFF_AL 4608
#define OFF_BH 9216
#define OFF_BL 13568
#define SMEM_WORDS 17920
#define SMEM_DYN (SMEM_WORDS*4)

// ---------------- scratch (static device globals; no allocation) -------------
__device__ float g_h   [NTOK*DIM];
__device__ float g_xln [NTOK*DIM];
__device__ float g_tmp [NTOK*DIM];
__device__ float g_H1  [(size_t)NA*FF];
__device__ float g_Y   [NA*DIM];
__device__ int   g_counts[NL*NE];
__device__ int   g_cursor[NL*NE];
__device__ int   g_off   [NL*(NE+1)];
__device__ int   g_tok [NA];
__device__ int   g_pair[NA];
__device__ float g_gw  [NA];
__device__ int   g_re  [NTOK*2];
__device__ float g_rw  [NTOK*2];

// ---------------- helpers ----------------------------------------------------
__device__ __forceinline__ void tf32split(float v, float& hi, float& lo) {
    uint32_t h;
    asm("cvt.rna.tf32.f32 %0, %1;" : "=r"(h) : "f"(v));
    hi = __uint_as_float(h);
    float r = v - hi;
    uint32_t l;
    asm("cvt.rna.tf32.f32 %0, %1;" : "=r"(l) : "f"(r));
    lo = __uint_as_float(l);
}

#define MMAT(acc, a, b0v, b1v) \
    asm volatile("mma.sync.aligned.m16n8k8.row.col.f32.tf32.tf32.f32 " \
        "{%0,%1,%2,%3},{%4,%5,%6,%7},{%8,%9},{%0,%1,%2,%3};" \
        : "+f"((acc)[0]), "+f"((acc)[1]), "+f"((acc)[2]), "+f"((acc)[3]) \
        : "r"((a)[0]), "r"((a)[1]), "r"((a)[2]), "r"((a)[3]), "r"(b0v), "r"(b1v))

__device__ __forceinline__ float warpSum(float v) {
    #pragma unroll
    for (int o = 16; o > 0; o >>= 1) v += __shfl_xor_sync(0xffffffffu, v, o);
    return v;
}

__global__ void zero_k() {
    int i = threadIdx.x;
    if (i < NL*NE) { g_counts[i] = 0; g_cursor[i] = 0; }
}

// ---------------- LayerNorm (+ optional gate / top-2 routing) ---------------
__global__ void ln_gate(const float* __restrict__ in, float* __restrict__ out,
                        const float* __restrict__ gam, const float* __restrict__ bet,
                        const float* __restrict__ wg, int layer)
{
    __shared__ float s[DIM];
    __shared__ float red[8];
    __shared__ float sstat;
    __shared__ float logits[NE];

    const int t = blockIdx.x, tid = threadIdx.x;
    const int lane = tid & 31, wid = tid >> 5;
    const float* row = in + (size_t)t*DIM;

    float lsum = 0.f;
    for (int d = tid; d < DIM; d += 256) { float v = row[d]; s[d] = v; lsum += v; }
    lsum = warpSum(lsum);
    if (lane == 0) red[wid] = lsum;
    __syncthreads();
    if (tid == 0) { float z = 0.f; for (int i = 0; i < 8; i++) z += red[i]; sstat = z / DIM; }
    __syncthreads();
    const float mu = sstat;

    float lvar = 0.f;
    for (int d = tid; d < DIM; d += 256) { float dv = s[d] - mu; lvar += dv*dv; }
    lvar = warpSum(lvar);
    __syncthreads();
    if (lane == 0) red[wid] = lvar;
    __syncthreads();
    if (tid == 0) { float z = 0.f; for (int i = 0; i < 8; i++) z += red[i]; sstat = rsqrtf(z / DIM + 1e-5f); }
    __syncthreads();
    const float rstd = sstat;

    for (int d = tid; d < DIM; d += 256) {
        float o = (s[d] - mu) * rstd * gam[d] + bet[d];
        out[(size_t)t*DIM + d] = o;
        s[d] = o;
    }
    if (!wg) return;
    __syncthreads();

    float acc = 0.f;
    for (int d = lane; d < DIM; d += 32) acc += s[d] * wg[d*NE + wid];
    acc = warpSum(acc);
    if (lane == 0) logits[wid] = acc;
    __syncthreads();

    if (tid == 0) {
        float v0 = -1e30f; int e0 = 0;
        #pragma unroll
        for (int e = 0; e < NE; e++) if (logits[e] > v0) { v0 = logits[e]; e0 = e; }
        float v1 = -1e30f; int e1 = 0;
        #pragma unroll
        for (int e = 0; e < NE; e++) if (e != e0 && logits[e] > v1) { v1 = logits[e]; e1 = e; }
        float ex  = expf(v1 - v0);
        float inv = 1.f / (1.f + ex);
        g_re[2*t] = e0;  g_re[2*t+1] = e1;
        g_rw[2*t] = inv; g_rw[2*t+1] = ex * inv;
        atomicAdd(&g_counts[layer*NE + e0], 1);
        atomicAdd(&g_counts[layer*NE + e1], 1);
    }
}

__global__ void scan_k(int layer) {
    if (threadIdx.x == 0) {
        int s = 0;
        for (int e = 0; e < NE; e++) { g_off[layer*(NE+1) + e] = s; s += g_counts[layer*NE + e]; }
        g_off[layer*(NE+1) + NE] = s;
    }
}

__global__ void scatter_k(int layer) {
    int t = blockIdx.x * blockDim.x + threadIdx.x;
    if (t >= NTOK) return;
    #pragma unroll
    for (int k = 0; k < 2; k++) {
        int e = g_re[2*t + k];
        int p = atomicAdd(&g_cursor[layer*NE + e], 1);
        int i = g_off[layer*(NE+1) + e] + p;
        g_tok[i]  = t;
        g_pair[i] = 2*t + k;
        g_gw[i]   = g_rw[2*t + k];
    }
}

__global__ void combine_k() {
    int idx = blockIdx.x * 256 + threadIdx.x;
    int t = idx / DIM, d = idx - t*DIM;
    float v = g_h[idx];
    v = v + g_Y[(size_t)(2*t)*DIM + d];
    v = v + g_Y[(size_t)(2*t + 1)*DIM + d];
    g_h[idx] = v;
}

// ---------------- 3xTF32 GEMM (128x128 tile, KC=32, direct-LDS fragments) ----
// C = A[M,K] * B[K,N] + bias;  A row-major, B row-major [K,N] (natural layout).
// mode 0: plain (A rows contiguous)
// mode 1: A rows gathered via g_tok; out = relu -> g_H1 fp32
// mode 2: A = g_H1 rows at base+lm; out = gw * (.) -> g_Y rows g_pair
__global__ void __launch_bounds__(256, 2)
tf_gemm(int mode, int layer,
        const float* __restrict__ A, const float* __restrict__ Bsrc,
        const float* __restrict__ bias, float* __restrict__ outF,
        int M, int Nn, int Kd)
{
    extern __shared__ float sm[];
    float* sAh = sm;
    float* sAl = sm + OFF_AL;
    float* sBh = sm + OFF_BH;
    float* sBl = sm + OFF_BL;

    const int tid = threadIdx.x;
    const int lane = tid & 31, wid = tid >> 5;
    const int warpM = wid >> 2, warpN = wid & 3;
    const int g = lane >> 2, tg = lane & 3;
    const int n0 = blockIdx.x*128, m0 = blockIdx.y*128;

    int Mloc = M, base = 0;
    if (mode == 1 || mode == 2) {
        int e = blockIdx.z;
        Mloc = g_counts[layer*NE + e];
        if (m0 >= Mloc) return;
        base = g_off[layer*(NE+1) + e];
        Bsrc += (size_t)(layer*NE + e) * FF * DIM;
        bias += (size_t)(layer*NE + e) * ((mode == 1) ? FF : DIM);
    } else {
        if (m0 >= M) return;
    }

    // A loader: thread -> row (tid>>1), half (tid&1) of 32-float slice
    const int ldrowA = tid >> 1, halfA = tid & 1;
    const float* pA = nullptr;
    {
        int lm = m0 + ldrowA;
        if (lm < Mloc) {
            int idx;
            if (mode == 1)      idx = g_tok[base + lm];
            else if (mode == 2) idx = base + lm;
            else                idx = lm;
            pA = A + (size_t)idx*Kd;
        }
    }
    // B loader: thread -> k-row (tid>>3), 4 float4s at cols (tid&7 + 8q)*4
    const int ldrowB = tid >> 3, colB = tid & 7;

    float acc[4][4][4];
    #pragma unroll
    for (int a = 0; a < 4; a++)
        #pragma unroll
        for (int b = 0; b < 4; b++)
            #pragma unroll
            for (int c = 0; c < 4; c++) acc[a][b][c] = 0.f;

    for (int kt = 0; kt < Kd; kt += 32) {
        __syncthreads();
        // ---- load A tile [128 x 32] with tf32 split ----
        #pragma unroll
        for (int q = 0; q < 4; q++) {
            float4 v = make_float4(0.f, 0.f, 0.f, 0.f);
            if (pA) v = *(const float4*)(pA + kt + (halfA*4 + q)*4);
            int bw = ldrowA*AW + halfA*16 + q*4;
            float h0,l0,h1,l1,h2,l2,h3,l3;
            tf32split(v.x, h0, l0); tf32split(v.y, h1, l1);
            tf32split(v.z, h2, l2); tf32split(v.w, h3, l3);
            sAh[bw]   = h0; sAh[bw+1] = h1; sAh[bw+2] = h2; sAh[bw+3] = h3;
            sAl[bw]   = l0; sAl[bw+1] = l1; sAl[bw+2] = l2; sAl[bw+3] = l3;
        }
        // ---- load B tile [32 x 128] with tf32 split ----
        #pragma unroll
        for (int q = 0; q < 4; q++) {
            int col = (colB + 8*q)*4;
            float4 v = *(const float4*)(Bsrc + (size_t)(kt + ldrowB)*Nn + n0 + col);
            int bw = ldrowB*BW + col;
            float h0,l0,h1,l1,h2,l2,h3,l3;
            tf32split(v.x, h0, l0); tf32split(v.y, h1, l1);
            tf32split(v.z, h2, l2); tf32split(v.w, h3, l3);
            sBh[bw]   = h0; sBh[bw+1] = h1; sBh[bw+2] = h2; sBh[bw+3] = h3;
            sBl[bw]   = l0; sBl[bw+1] = l1; sBl[bw+2] = l2; sBl[bw+3] = l3;
        }
        __syncthreads();

        // ---- 4 k8-steps of mma ----
        #pragma unroll
        for (int ks = 0; ks < 4; ks++) {
            const int k0 = ks*8;
            uint32_t bh0[4], bh1[4], bl0[4], bl1[4];
            #pragma unroll
            for (int nt = 0; nt < 4; nt++) {
                int n = warpN*32 + nt*8 + g;
                bh0[nt] = __float_as_uint(sBh[(k0+tg)*BW + n]);
                bh1[nt] = __float_as_uint(sBh[(k0+tg+4)*BW + n]);
                bl0[nt] = __float_as_uint(sBl[(k0+tg)*BW + n]);
                bl1[nt] = __float_as_uint(sBl[(k0+tg+4)*BW + n]);
            }
            #pragma unroll
            for (int mt = 0; mt < 4; mt++) {
                int rowa = warpM*64 + mt*16 + g;
                int c = k0 + tg;
                uint32_t ah[4], al[4];
                ah[0] = __float_as_uint(sAh[rowa*AW + c]);
                ah[1] = __float_as_uint(sAh[(rowa+8)*AW + c]);
                ah[2] = __float_as_uint(sAh[rowa*AW + c + 4]);
                ah[3] = __float_as_uint(sAh[(rowa+8)*AW + c + 4]);
                al[0] = __float_as_uint(sAl[rowa*AW + c]);
                al[1] = __float_as_uint(sAl[(rowa+8)*AW + c]);
                al[2] = __float_as_uint(sAl[rowa*AW + c + 4]);
                al[3] = __float_as_uint(sAl[(rowa+8)*AW + c + 4]);
                #pragma unroll
                for (int nt = 0; nt < 4; nt++) {
                    MMAT(acc[mt][nt], ah, bh0[nt], bh1[nt]);
                    MMAT(acc[mt][nt], ah, bl0[nt], bl1[nt]);
                    MMAT(acc[mt][nt], al, bh0[nt], bh1[nt]);
                }
            }
        }
    }

    // ---------------- epilogue ----------------
    #pragma unroll
    for (int mt = 0; mt < 4; mt++) {
        #pragma unroll
        for (int half_m = 0; half_m < 2; half_m++) {
            const int mrow = m0 + warpM*64 + mt*16 + g + half_m*8;
            if (mrow >= Mloc) continue;
            float gww = 1.f;
            size_t rowoff;
            if (mode == 1) {
                rowoff = (size_t)(base + mrow) * FF;
            } else if (mode == 2) {
                int gi = base + mrow;
                gww = g_gw[gi];
                rowoff = (size_t)g_pair[gi] * DIM;
            } else {
                rowoff = (size_t)mrow * Nn;
            }
            #pragma unroll
            for (int nt = 0; nt < 4; nt++) {
                const int col = n0 + warpN*32 + nt*8 + tg*2;
                float2 bs = *(const float2*)(bias + col);
                float v0 = acc[mt][nt][2*half_m]     + bs.x;
                float v1 = acc[mt][nt][2*half_m + 1] + bs.y;
                if (mode == 1) {
                    v0 = fmaxf(v0, 0.f); v1 = fmaxf(v1, 0.f);
                    *(float2*)(g_H1 + rowoff + col) = make_float2(v0, v1);
                } else if (mode == 2) {
                    *(float2*)(g_Y + rowoff + col) = make_float2(gww*v0, gww*v1);
                } else {
                    *(float2*)(outF + rowoff + col) = make_float2(v0, v1);
                }
            }
        }
    }
}

// ---------------- host -------------------------------------------------------
extern "C" void kernel_launch(void* const* d_in, const int* in_sizes, int n_in,
                              void* d_out, int out_size)
{
    (void)in_sizes; (void)n_in; (void)out_size;
    const float* x      = (const float*)d_in[0];
    const float* w_in   = (const float*)d_in[1];
    const float* b_in   = (const float*)d_in[2];
    const float* gi     = (const float*)d_in[3];
    const float* bi     = (const float*)d_in[4];
    const float* g_lnp  = (const float*)d_in[5];
    const float* be_lnp = (const float*)d_in[6];
    const float* wgp    = (const float*)d_in[7];
    const float* w1p    = (const float*)d_in[8];
    const float* b1p    = (const float*)d_in[9];
    const float* w2p    = (const float*)d_in[10];
    const float* b2p    = (const float*)d_in[11];
    const float* w_out  = (const float*)d_in[12];
    const float* b_out  = (const float*)d_in[13];
    const float* g_o    = (const float*)d_in[14];
    const float* be_o   = (const float*)d_in[15];

    float *hP, *tmpP, *xlnP, *h1P;
    cudaGetSymbolAddress((void**)&hP,   g_h);
    cudaGetSymbolAddress((void**)&tmpP, g_tmp);
    cudaGetSymbolAddress((void**)&xlnP, g_xln);
    cudaGetSymbolAddress((void**)&h1P,  g_H1);

    cudaFuncSetAttribute(tf_gemm, cudaFuncAttributeMaxDynamicSharedMemorySize, SMEM_DYN);

    zero_k<<<1, 64>>>();

    // input projection + LN -> residual h
    tf_gemm<<<dim3(DIM/128, NTOK/128), 256, SMEM_DYN>>>(
        0, 0, x, w_in, b_in, tmpP, NTOK, DIM, DIM);
    ln_gate<<<NTOK, 256>>>(tmpP, hP, gi, bi, nullptr, 0);

    for (int l = 0; l < NL; l++) {
        ln_gate<<<NTOK, 256>>>(hP, xlnP, g_lnp + (size_t)l*DIM, be_lnp + (size_t)l*DIM,
                               wgp + (size_t)l*DIM*NE, l);
        scan_k<<<1, 32>>>(l);
        scatter_k<<<NTOK/256, 256>>>(l);
        tf_gemm<<<dim3(FF/128, NTOK/128, NE), 256, SMEM_DYN>>>(
            1, l, xlnP, w1p, b1p, nullptr, 0, FF, DIM);
        tf_gemm<<<dim3(DIM/128, NTOK/128, NE), 256, SMEM_DYN>>>(
            2, l, h1P, w2p, b2p, nullptr, 0, DIM, FF);
        combine_k<<<NTOK*DIM/256, 256>>>();
    }

    // output projection + LN -> d_out
    tf_gemm<<<dim3(DIM/128, NTOK/128), 256, SMEM_DYN>>>(
        0, 0, hP, w_out, b_out, tmpP, NTOK, DIM, DIM);
    ln_gate<<<NTOK, 256>>>(tmpP, (float*)d_out, g_o, be_o, nullptr, 0);
}